// round 12
// baseline (speedup 1.0000x reference)
#include <cuda_runtime.h>
#include <cstdint>

// DETR-style postprocess, element-partitioned persistent-ish design:
//   logits [256,1000,80] f32, boxes [256,1000,4] f32 (cxcywh)
//   -> labels [256,300], boxes_xyxy [256,300,4], scores [256,300]
// Output concatenated flat f32: labels | boxes | scores. (verified R3)
//
// 296 blocks (=2 per SM exactly) x 1024 threads. Each block streams a
// contiguous chunk of the GLOBAL logits stream (chunks cross batch
// boundaries); candidates go to per-batch global buffers. The last block
// to finish a batch ranks it.

#define BATCH    256
#define QQ       1000
#define CC       80
#define NELEM    80000
#define NV4      20000                 // float4 per batch
#define NV4TOT   (BATCH * NV4)         // 5,120,000
#define KTOP     300
#define CAP      4096
#define NBINS    2048
#define T_STATIC 2.5f

#define NT       1024
#define GRID     296
#define QCH      (NV4TOT / GRID)       // 17297
#define RCH      (NV4TOT % GRID)       // 88
#define SPLIT    (RCH * (QCH + 1))     // 1,522,224  (f4 index where chunk size drops)

#define LBL_OFF  0
#define BOX_OFF  (BATCH * KTOP)            // 76800
#define SCR_OFF  (BATCH * KTOP * 5)        // 384000

// Global scratch (zero-init at module load; rank owner resets per replay)
__device__ unsigned long long g_pack[BATCH][CAP];
__device__ int g_cnt[BATCH];
__device__ int g_done[BATCH];

__device__ __forceinline__ unsigned f2key(float x) {
    unsigned bb = __float_as_uint(x);
    return (bb & 0x80000000u) ? ~bb : (bb | 0x80000000u);
}
__device__ __forceinline__ float key2f(unsigned k) {
    unsigned bb = (k & 0x80000000u) ? (k & 0x7FFFFFFFu) : ~k;
    return __uint_as_float(bb);
}
// which block owns f4 index x (inverse of the balanced partition)
__device__ __forceinline__ int blk_of(int x) {
    return (x < SPLIT) ? (x / (QCH + 1)) : (RCH + (x - SPLIT) / QCH);
}

__device__ __forceinline__ void push_cand(int x /*f4 idx*/, int j, float v) {
    unsigned gi = (unsigned)x * 4u + (unsigned)j;     // global element idx
    int bb = (int)(gi / (unsigned)NELEM);             // batch
    unsigned li = gi - (unsigned)bb * (unsigned)NELEM; // local idx in batch
    int pos = atomicAdd(&g_cnt[bb], 1);
    if (pos < CAP)
        g_pack[bb][pos] = ((unsigned long long)f2key(v) << 32)
                          | (unsigned long long)(~li);
}

__global__ __launch_bounds__(NT, 2)
void postproc_kernel(const float* __restrict__ logits,
                     const float* __restrict__ boxes,
                     float* __restrict__ out)
{
    __shared__ __align__(16) unsigned long long s_pack[CAP];  // 32 KB
    __shared__ int s_cnt, s_M;
    __shared__ int s_b1, s_gt, s_cg, s_b2;
    __shared__ int s_nown;
    __shared__ int s_own[4];

    const int blk = blockIdx.x;
    const int tid = threadIdx.x;
    const float4* lg4 = (const float4*)logits;

    const int start = blk * QCH + min(blk, RCH);
    const int n     = QCH + (blk < RCH ? 1 : 0);      // 17297 or 17298

    // ---------------- stream this chunk (MLP=4 front-batched, proven body) ----
    #pragma unroll 1
    for (int it = 0; it < 4; it++) {                  // 4 * 4096 = 16384 f4
        int base = start + it * (4 * NT) + tid;
        float4 v0 = lg4[base];
        float4 v1 = lg4[base + NT];
        float4 v2 = lg4[base + 2 * NT];
        float4 v3 = lg4[base + 3 * NT];
        float vv[16] = {v0.x, v0.y, v0.z, v0.w,  v1.x, v1.y, v1.z, v1.w,
                        v2.x, v2.y, v2.z, v2.w,  v3.x, v3.y, v3.z, v3.w};
        #pragma unroll
        for (int k = 0; k < 16; k++)
            if (vv[k] > T_STATIC)
                push_cand(base + (k >> 2) * NT, k & 3, vv[k]);
    }
    {   // tail: rem = n - 16384 (913 or 914) < NT -> single guarded load
        int rem = n - 4 * (4 * NT);
        if (tid < rem) {
            int x = start + 4 * (4 * NT) + tid;
            float4 v = lg4[x];
            float vv[4] = {v.x, v.y, v.z, v.w};
            #pragma unroll
            for (int j = 0; j < 4; j++)
                if (vv[j] > T_STATIC) push_cand(x, j, vv[j]);
        }
    }

    // ---------------- publish done, claim ownership of finished batches -------
    __threadfence();
    __syncthreads();
    if (tid == 0) {
        int b_lo = start / NV4;
        int b_hi = (start + n - 1) / NV4;             // chunk spans <= 2 batches
        int cnt = 0;
        for (int b = b_lo; b <= b_hi; b++) {
            int expect = blk_of(b * NV4 + NV4 - 1) - blk_of(b * NV4) + 1;
            int old = atomicAdd(&g_done[b], 1);
            if (old == expect - 1) s_own[cnt++] = b;
        }
        s_nown = cnt;
    }
    __syncthreads();
    const int nown = s_nown;

    // ---------------- rank each owned batch ----------------------------------
    for (int t = 0; t < nown; t++) {
        const int b = s_own[t];
        const float4* blg4 = (const float4*)(logits + (size_t)b * NELEM);
        __threadfence();                 // see other blocks' candidate stores
        __syncthreads();
        if (tid == 0) s_M = atomicAdd(&g_cnt[b], 0);
        __syncthreads();
        int M = s_M;

        if (M >= KTOP && M <= CAP) {
            for (int i = tid; i < M; i += NT)
                s_pack[i] = __ldcg(&g_pack[b][i]);
            __syncthreads();
        } else {
            // -------- exact 2-level radix fallback over batch b --------
            unsigned* s_hist = (unsigned*)s_pack;     // overlay
            for (int i = tid; i < NBINS; i += NT) s_hist[i] = 0;
            __syncthreads();
            for (int i = tid; i < NV4; i += NT) {
                float4 v = blg4[i];
                float vv[4] = {v.x, v.y, v.z, v.w};
                #pragma unroll
                for (int j = 0; j < 4; j++)
                    atomicAdd(&s_hist[f2key(vv[j]) >> 21], 1u);
            }
            __syncthreads();
            if (tid == 0) {
                int acc = 0, b1 = 0;
                for (int bin = NBINS - 1; bin >= 0; bin--) {
                    int c = (int)s_hist[bin];
                    if (acc + c >= KTOP) { b1 = bin; break; }
                    acc += c;
                }
                s_b1 = b1; s_gt = acc; s_cg = acc + (int)s_hist[b1];
                s_cnt = 0;
            }
            __syncthreads();
            const int b1 = s_b1;

            if (s_cg <= CAP) {
                __syncthreads();
                for (int i = tid; i < NV4; i += NT) {
                    float4 v = blg4[i];
                    float vv[4] = {v.x, v.y, v.z, v.w};
                    #pragma unroll
                    for (int j = 0; j < 4; j++) {
                        unsigned key = f2key(vv[j]);
                        if ((int)(key >> 21) >= b1) {
                            int pos = atomicAdd(&s_cnt, 1);
                            unsigned idx = (unsigned)(i * 4 + j);
                            s_pack[pos] = ((unsigned long long)key << 32)
                                          | (unsigned long long)(~idx);
                        }
                    }
                }
                __syncthreads();
                M = s_cnt;
            } else {
                for (int i = tid; i < NBINS; i += NT) s_hist[i] = 0;
                __syncthreads();
                for (int i = tid; i < NV4; i += NT) {
                    float4 v = blg4[i];
                    float vv[4] = {v.x, v.y, v.z, v.w};
                    #pragma unroll
                    for (int j = 0; j < 4; j++) {
                        unsigned key = f2key(vv[j]);
                        if ((int)(key >> 21) == b1)
                            atomicAdd(&s_hist[(key >> 10) & 0x7FFu], 1u);
                    }
                }
                __syncthreads();
                if (tid == 0) {
                    int need = KTOP - s_gt;
                    int acc = 0, b2 = 0;
                    for (int bin = NBINS - 1; bin >= 0; bin--) {
                        int c = (int)s_hist[bin];
                        if (acc + c >= need) { b2 = bin; break; }
                        acc += c;
                    }
                    s_b2 = b2; s_cnt = 0;
                }
                __syncthreads();
                const int b2 = s_b2;
                for (int i = tid; i < NV4; i += NT) {
                    float4 v = blg4[i];
                    float vv[4] = {v.x, v.y, v.z, v.w};
                    #pragma unroll
                    for (int j = 0; j < 4; j++) {
                        unsigned key = f2key(vv[j]);
                        int hb = (int)(key >> 21);
                        bool take = (hb > b1) ||
                                    (hb == b1 && (int)((key >> 10) & 0x7FFu) >= b2);
                        if (take) {
                            int pos = atomicAdd(&s_cnt, 1);
                            if (pos < CAP) {
                                unsigned idx = (unsigned)(i * 4 + j);
                                s_pack[pos] = ((unsigned long long)key << 32)
                                              | (unsigned long long)(~idx);
                            }
                        }
                    }
                }
                __syncthreads();
                M = min(s_cnt, CAP);
            }
        }

        // zero pad (sorts below all real packs)
        if (tid == 0 && M < CAP) s_pack[M] = 0ULL;
        __syncthreads();
        const int Mpair = (M + 1) >> 1;
        const ulonglong2* sp2 = (const ulonglong2*)s_pack;

        // exact ranking: descending key, lower idx first on ties
        for (int i = tid; i < M; i += NT) {
            unsigned long long pi = s_pack[i];
            int r = 0;
            for (int j = 0; j < Mpair; j++) {
                ulonglong2 pj = sp2[j];
                r += (pj.x > pi) + (pj.y > pi);
            }
            if (r < KTOP) {
                unsigned key = (unsigned)(pi >> 32);
                unsigned idx = ~(unsigned)(pi & 0xFFFFFFFFull);
                int q = (int)(idx / CC);
                int c = (int)(idx % CC);
                float lv = key2f(key);
                float score = 1.0f / (1.0f + expf(-lv));

                size_t slot = (size_t)b * KTOP + r;
                out[LBL_OFF + slot] = (float)c;
                out[SCR_OFF + slot] = score;

                float4 bx = ((const float4*)boxes)[(size_t)b * QQ + q];
                float4 o;
                o.x = bx.x - 0.5f * bx.z;
                o.y = bx.y - 0.5f * bx.w;
                o.z = bx.x + 0.5f * bx.z;
                o.w = bx.y + 0.5f * bx.w;
                ((float4*)(out + BOX_OFF))[slot] = o;
            }
        }
        __syncthreads();
        if (tid == 0) {            // reset batch state for next graph replay
            g_cnt[b]  = 0;
            g_done[b] = 0;
        }
    }
}

extern "C" void kernel_launch(void* const* d_in, const int* in_sizes, int n_in,
                              void* d_out, int out_size)
{
    const float* logits = (const float*)d_in[0];
    const float* boxes  = (const float*)d_in[1];
    float* out = (float*)d_out;

    postproc_kernel<<<GRID, NT>>>(logits, boxes, out);
}

// round 13
// speedup vs baseline: 2.7909x; 2.7909x over previous
#include <cuda_runtime.h>
#include <cstdint>

// DETR-style postprocess (fused, block-per-batch — proven R8 skeleton):
//   logits [256,1000,80] f32, boxes [256,1000,4] f32 (cxcywh)
//   -> labels [256,300], boxes_xyxy [256,300,4], scores [256,300]
// Output concatenated flat f32: labels | boxes | scores. (verified R3)

#define BATCH      256
#define QQ         1000
#define CC         80
#define NELEM      80000      // QQ*CC per batch
#define NV4        20000      // NELEM/4 (float4 units)
#define KTOP       300
#define CAP        4096
#define NBINS      2048       // 11-bit radix level
#define NTHREADS   1024
#define T_STATIC   2.5f

#define LBL_OFF    0
#define BOX_OFF    (BATCH * KTOP)            // 76800
#define SCR_OFF    (BATCH * KTOP * 5)        // 384000

// Monotone float->uint key (ascending order preserved)
__device__ __forceinline__ unsigned f2key(float x) {
    unsigned b = __float_as_uint(x);
    return (b & 0x80000000u) ? ~b : (b | 0x80000000u);
}
__device__ __forceinline__ float key2f(unsigned k) {
    unsigned b = (k & 0x80000000u) ? (k & 0x7FFFFFFFu) : ~k;
    return __uint_as_float(b);
}
__device__ __forceinline__ float max4(float4 v) {
    return fmaxf(fmaxf(v.x, v.y), fmaxf(v.z, v.w));
}

__global__ __launch_bounds__(NTHREADS, 2)
void postproc_topk_kernel(const float* __restrict__ logits,
                          const float* __restrict__ boxes,
                          float* __restrict__ out)
{
    __shared__ __align__(16) unsigned long long s_pack[CAP];  // (key<<32) | ~idx
    __shared__ unsigned s_hist[NBINS];                         // fallback only
    __shared__ int s_cnt;
    __shared__ int s_b1, s_gt, s_b2;

    const int b   = blockIdx.x;
    const int tid = threadIdx.x;
    const float4* lg4 = (const float4*)(logits + (size_t)b * NELEM);

    if (tid == 0) s_cnt = 0;
    __syncthreads();

    // ---------- Primary path: stream, MLP=4, max-tree screen ----------
    // 20000 float4 = 4 full tiles of 4096 + tail tile (3616).
    #pragma unroll 1
    for (int it = 0; it < 4; it++) {
        int base = it * 4096 + tid;
        // 4 independent streaming loads (front-batched, evict-first)
        float4 v0 = __ldcs(&lg4[base]);
        float4 v1 = __ldcs(&lg4[base + 1024]);
        float4 v2 = __ldcs(&lg4[base + 2048]);
        float4 v3 = __ldcs(&lg4[base + 3072]);

        // screen: one branch for all 16 values (taken ~10% of thread-iters)
        float mx = fmaxf(fmaxf(max4(v0), max4(v1)), fmaxf(max4(v2), max4(v3)));
        if (mx > T_STATIC) {
            float vv[16] = {v0.x, v0.y, v0.z, v0.w,  v1.x, v1.y, v1.z, v1.w,
                            v2.x, v2.y, v2.z, v2.w,  v3.x, v3.y, v3.z, v3.w};
            #pragma unroll
            for (int k = 0; k < 16; k++) {
                if (vv[k] > T_STATIC) {
                    int pos = atomicAdd(&s_cnt, 1);
                    if (pos < CAP) {
                        unsigned idx = (unsigned)((base + (k >> 2) * 1024) * 4 + (k & 3));
                        s_pack[pos] = ((unsigned long long)f2key(vv[k]) << 32)
                                      | (unsigned long long)(~idx);
                    }
                }
            }
        }
    }
    {   // tail tile: base in [16384, 20479]; only 4th load can go OOB (tid>=544)
        int base = 16384 + tid;
        float4 v0 = __ldcs(&lg4[base]);
        float4 v1 = __ldcs(&lg4[base + 1024]);
        float4 v2 = __ldcs(&lg4[base + 2048]);
        float4 v3 = make_float4(-1e30f, -1e30f, -1e30f, -1e30f);
        if (tid < 544) v3 = __ldcs(&lg4[base + 3072]);

        float mx = fmaxf(fmaxf(max4(v0), max4(v1)), fmaxf(max4(v2), max4(v3)));
        if (mx > T_STATIC) {
            float vv[16] = {v0.x, v0.y, v0.z, v0.w,  v1.x, v1.y, v1.z, v1.w,
                            v2.x, v2.y, v2.z, v2.w,  v3.x, v3.y, v3.z, v3.w};
            #pragma unroll
            for (int k = 0; k < 16; k++) {
                if (vv[k] > T_STATIC) {
                    int pos = atomicAdd(&s_cnt, 1);
                    if (pos < CAP) {
                        unsigned idx = (unsigned)((base + (k >> 2) * 1024) * 4 + (k & 3));
                        s_pack[pos] = ((unsigned long long)f2key(vv[k]) << 32)
                                      | (unsigned long long)(~idx);
                    }
                }
            }
        }
    }
    __syncthreads();
    int M = s_cnt;

    // ---------- Fallback: exact 2-level radix select (statistically never) ----------
    if (M < KTOP || M > CAP) {
        for (int i = tid; i < NBINS; i += NTHREADS) s_hist[i] = 0;
        __syncthreads();
        for (int i = tid; i < NV4; i += NTHREADS) {
            float4 v = lg4[i];
            float vv[4] = {v.x, v.y, v.z, v.w};
            #pragma unroll
            for (int j = 0; j < 4; j++)
                atomicAdd(&s_hist[f2key(vv[j]) >> 21], 1u);
        }
        __syncthreads();
        if (tid == 0) {
            int acc = 0, b1 = 0;
            for (int bin = NBINS - 1; bin >= 0; bin--) {
                int c = (int)s_hist[bin];
                if (acc + c >= KTOP) { b1 = bin; break; }
                acc += c;
            }
            s_b1 = b1; s_gt = acc;
        }
        __syncthreads();
        const int b1 = s_b1;
        const int cnt_ge = s_gt + (int)s_hist[b1];

        if (cnt_ge <= CAP) {
            if (tid == 0) s_cnt = 0;
            __syncthreads();
            for (int i = tid; i < NV4; i += NTHREADS) {
                float4 v = lg4[i];
                float vv[4] = {v.x, v.y, v.z, v.w};
                #pragma unroll
                for (int j = 0; j < 4; j++) {
                    unsigned key = f2key(vv[j]);
                    if ((int)(key >> 21) >= b1) {
                        int pos = atomicAdd(&s_cnt, 1);
                        unsigned idx = (unsigned)(i * 4 + j);
                        s_pack[pos] = ((unsigned long long)key << 32)
                                      | (unsigned long long)(~idx);
                    }
                }
            }
            __syncthreads();
            M = s_cnt;
        } else {
            for (int i = tid; i < NBINS; i += NTHREADS) s_hist[i] = 0;
            __syncthreads();
            for (int i = tid; i < NV4; i += NTHREADS) {
                float4 v = lg4[i];
                float vv[4] = {v.x, v.y, v.z, v.w};
                #pragma unroll
                for (int j = 0; j < 4; j++) {
                    unsigned key = f2key(vv[j]);
                    if ((int)(key >> 21) == b1)
                        atomicAdd(&s_hist[(key >> 10) & 0x7FFu], 1u);
                }
            }
            __syncthreads();
            if (tid == 0) {
                int need = KTOP - s_gt;
                int acc = 0, b2 = 0;
                for (int bin = NBINS - 1; bin >= 0; bin--) {
                    int c = (int)s_hist[bin];
                    if (acc + c >= need) { b2 = bin; break; }
                    acc += c;
                }
                s_b2 = b2; s_cnt = 0;
            }
            __syncthreads();
            const int b2 = s_b2;
            for (int i = tid; i < NV4; i += NTHREADS) {
                float4 v = lg4[i];
                float vv[4] = {v.x, v.y, v.z, v.w};
                #pragma unroll
                for (int j = 0; j < 4; j++) {
                    unsigned key = f2key(vv[j]);
                    int hb = (int)(key >> 21);
                    bool take = (hb > b1) ||
                                (hb == b1 && (int)((key >> 10) & 0x7FFu) >= b2);
                    if (take) {
                        int pos = atomicAdd(&s_cnt, 1);
                        if (pos < CAP) {
                            unsigned idx = (unsigned)(i * 4 + j);
                            s_pack[pos] = ((unsigned long long)key << 32)
                                          | (unsigned long long)(~idx);
                        }
                    }
                }
            }
            __syncthreads();
            M = min(s_cnt, CAP);
        }
    }

    // pad one zero pack so the paired inner loop can read an even count
    // (zero pack sorts below every real pack -> never affects ranks)
    if (tid == 0 && M < CAP) s_pack[M] = 0ULL;
    __syncthreads();
    const int Mpair = (M + 1) >> 1;
    const ulonglong2* sp2 = (const ulonglong2*)s_pack;

    // ---------- Exact ranking (descending key, lower idx first on ties) ----------
    for (int i = tid; i < M; i += NTHREADS) {
        unsigned long long pi = s_pack[i];
        int r = 0;
        for (int j = 0; j < Mpair; j++) {
            ulonglong2 pj = sp2[j];
            r += (pj.x > pi) + (pj.y > pi);
        }
        if (r < KTOP) {
            unsigned key = (unsigned)(pi >> 32);
            unsigned idx = ~(unsigned)(pi & 0xFFFFFFFFull);
            int q = (int)(idx / CC);
            int c = (int)(idx % CC);
            float lv = key2f(key);
            float score = 1.0f / (1.0f + expf(-lv));

            size_t slot = (size_t)b * KTOP + r;
            out[LBL_OFF + slot] = (float)c;
            out[SCR_OFF + slot] = score;

            float4 bx = ((const float4*)boxes)[(size_t)b * QQ + q];
            float4 o;
            o.x = bx.x - 0.5f * bx.z;
            o.y = bx.y - 0.5f * bx.w;
            o.z = bx.x + 0.5f * bx.z;
            o.w = bx.y + 0.5f * bx.w;
            ((float4*)(out + BOX_OFF))[slot] = o;
        }
    }
}

extern "C" void kernel_launch(void* const* d_in, const int* in_sizes, int n_in,
                              void* d_out, int out_size)
{
    const float* logits = (const float*)d_in[0];
    const float* boxes  = (const float*)d_in[1];
    float* out = (float*)d_out;
    postproc_topk_kernel<<<BATCH, NTHREADS>>>(logits, boxes, out);
}